// round 8
// baseline (speedup 1.0000x reference)
#include <cuda_runtime.h>
#include <cuda_bf16.h>
#include <cstdint>
#include <cstddef>

#define NB   1024
#define NM   14
#define NBLK 148
#define WPB  7                  // warps (=buckets) per block
#define NTHR (WPB * 32)         // 224

// Inflow ping-pong buffers + barrier state. Self-resetting per launch:
// zeros written at start / consumer-zeroed per layer; g_ctr/g_exit reset by
// the last-exiting block so graph replays start clean.
__device__ float    g_inflow[2][NB];
__device__ unsigned g_ctr;
__device__ unsigned g_exit;

__device__ __forceinline__ float sqrt_approx(float x) {
    float y; asm("sqrt.approx.f32 %0, %1;" : "=f"(y) : "f"(x)); return y;
}
__device__ __forceinline__ unsigned ld_acq(const unsigned* p) {
    unsigned v; asm volatile("ld.acquire.gpu.global.u32 %0, [%1];" : "=r"(v) : "l"(p)); return v;
}
__device__ __forceinline__ unsigned warp_min_u32(unsigned v) {
    unsigned r; asm("redux.sync.min.u32 %0, %1, 0xffffffff;" : "=r"(r) : "r"(v)); return r;
}

// Grid barrier: all 148 blocks resident (1 block/SM). Monotonic counter.
__device__ __forceinline__ void grid_barrier(unsigned target) {
    __syncthreads();
    if (threadIdx.x == 0) {
        __threadfence();
        atomicAdd(&g_ctr, 1u);
        while (ld_acq(&g_ctr) < target) { }
    }
    __syncthreads();
}

// Stage a bucket row into registers: lane holds spigots {w*32+lane} for all
// 32 windows. Also computes mb: lane w = min(bh of window w) via redux
// (bh >= 0 so uint ordering == float ordering). All loads independent (high
// MLP); redux chain is off the serial path (done before the grid barrier).
__device__ __forceinline__ void stage_regs(const float2* __restrict__ S2,
                                           const float* __restrict__ T,
                                           int lane, float bh[32], float cc[32],
                                           float& mb) {
    const float SQ2G = 4.4271887242357310f;   // sqrt(2*9.8)
    #pragma unroll
    for (int w = 0; w < 32; ++w) {
        float2 p = S2[w * 32 + lane];
        bh[w] = p.x; cc[w] = p.y;
    }
    #pragma unroll
    for (int w = 0; w < 32; ++w)
        cc[w] = cc[w] * T[w * 32 + lane] * SQ2G;
    unsigned m = 0xFFFFFFFFu;
    #pragma unroll
    for (int w = 0; w < 32; ++w) {
        unsigned r = warp_min_u32(__float_as_uint(bh[w]));
        m = (lane == w) ? r : m;
    }
    mb = __uint_as_float(m);
}

// Exact sequential recurrence. Dry spigots give q==0 and leave H_eff
// bit-identical -> only firing spigots (lowest index first via ballot) are
// serialized; windows drain in index order (reference order preserved).
// wf = ballot(H_eff > mb) marks fire-eligible windows once; H_eff is
// monotone nonincreasing so stale bits only cost one empty ballot.
template <bool ATOMIC>
__device__ float chain_regs(int lane, float H0, float inflow,
                            const float bh[32], const float cc[32], float mb,
                            float* __restrict__ nxt)
{
    const unsigned FULL = 0xFFFFFFFFu;
    // spigot 0: H_eff = H0 + inflow (reference quirk)
    float bh0 = __shfl_sync(FULL, bh[0], 0);
    float cc0 = __shfl_sync(FULL, cc[0], 0);
    float h0  = fmaxf((H0 + inflow) - bh0, 0.0f);
    float q0  = cc0 * sqrt_approx(h0);
    float cum = q0;
    float H_eff = fmaf(-0.5f, cum, H0);
    if (lane == 0 && q0 != 0.0f) {
        if (ATOMIC) atomicAdd(&nxt[0], q0); else nxt[0] = q0;
    }

    unsigned wf = __ballot_sync(FULL, H_eff > mb);   // fire-eligible windows
    #pragma unroll
    for (int w = 0; w < 32; ++w) {
        if (!(wf & (1u << w))) continue;             // dry window: ~6 cy skip
        float qacc = 0.0f;
        unsigned rem = (w == 0) ? 0xFFFFFFFEu : FULL;   // spigot 0 done
        while (true) {
            float h = H_eff - bh[w];
            unsigned fire = __ballot_sync(FULL, h > 0.0f) & rem;
            if (!fire) break;
            float q = cc[w] * sqrt_approx(h);        // speculative
            int f = __ffs(fire) - 1;                 // lowest firing spigot
            float qf = __shfl_sync(FULL, q, f);
            cum += qf;
            H_eff = fmaf(-0.5f, cum, H0);
            qacc = (lane == f) ? qf : qacc;
            rem &= (0xFFFFFFFEu << f);
        }
        if (qacc != 0.0f) {
            if (ATOMIC) atomicAdd(&nxt[w * 32 + lane], qacc);
            else        nxt[w * 32 + lane] = qacc;
        }
    }
    return cum;
}

// ---------------------------------------------------------------------------
// Persistent kernel: 148 blocks x 224 threads, 1 block/SM, register-resident
// chains. Layer l+1's staging loads issue right after chain l and fly during
// the grid barrier (14.5 MB chip-wide in flight -> DRAM-rate streaming, no
// prefetch instructions, no duplicate traffic).
// ---------------------------------------------------------------------------
__global__ void __launch_bounds__(NTHR, 1)
k_cascade(const float* __restrict__ H0p,   const float* __restrict__ H_mid,
          const float* __restrict__ H_last,const float* __restrict__ S0,
          const float* __restrict__ S_mid, const float* __restrict__ S_last,
          const float* __restrict__ theta0,const float* __restrict__ theta_mid,
          const float* __restrict__ theta_last, const float* __restrict__ precip,
          float* __restrict__ out)
{
    const int tid  = threadIdx.x;
    const int lane = tid & 31;
    const int w    = tid >> 5;                    // 0..6
    const int b    = blockIdx.x * WPB + w;        // bucket id (may be >= NB)

    if (lane == 0 && b < NB) { g_inflow[0][b] = 0.0f; g_inflow[1][b] = 0.0f; }

    const float pre      = precip[0];
    const float p_layer  = pre * (1.0f / 16.0f);
    const float p_bucket = p_layer * (1.0f / 1024.0f);

    float bh[32], cc[32], mb;

    // stage layer 0 immediately (loads fly during barrier + head chain)
    if (b < NB)
        stage_regs((const float2*)S_mid + (size_t)b * NB,
                   theta_mid + (size_t)b * NB, lane, bh, cc, mb);

    unsigned phase = 1;
    grid_barrier(NBLK * phase); ++phase;          // zeros visible

    // head bucket (block 0 warp 0) -> plain stores into g_inflow[0]
    if (blockIdx.x == 0 && w == 0) {
        float hbh[32], hcc[32], hmb;
        stage_regs((const float2*)S0, theta0, lane, hbh, hcc, hmb);
        float H0 = H0p[0];
        float cum = chain_regs<false>(lane, H0, p_layer, hbh, hcc, hmb, g_inflow[0]);
        if (lane == 0) out[0] = (H0 - cum) + p_layer;
    }

    grid_barrier(NBLK * phase); ++phase;          // q0 visible

    for (int l = 0; l < NM; ++l) {
        const int cur = l & 1;
        if (b < NB) {
            float inf0 = 0.0f;
            if (lane == 0) { inf0 = g_inflow[cur][b]; g_inflow[cur][b] = 0.0f; }
            float H0 = H_mid[(size_t)l * NB + b];
            float inflow = __shfl_sync(0xFFFFFFFFu, inf0, 0) + p_bucket;
            float cum = chain_regs<true>(lane, H0, inflow, bh, cc, mb,
                                         g_inflow[cur ^ 1]);
            if (lane == 0) out[1 + l * NB + b] = (H0 - cum) + inflow;
        }
        // stage l+1 BEFORE the barrier: loads overlap barrier + next waits
        if (l + 1 < NM && b < NB) {
            size_t row = (size_t)(l + 1) * NB + (size_t)b;
            stage_regs((const float2*)S_mid + row * NB,
                       theta_mid + row * NB, lane, bh, cc, mb);
        }
        grid_barrier(NBLK * phase); ++phase;      // layer-l atomics visible
    }

    // last layer: one outlet spigot per bucket (final inflows in g_inflow[0])
    if (b < NB && lane == 0) {
        float inflow = g_inflow[0][b] + p_bucket;
        float H0 = H_last[b];
        float sh = S_last[2 * b + 0];
        float a  = S_last[2 * b + 1];
        float h  = fmaxf((H0 + inflow) - sh, 0.0f);
        float q  = theta_last[b] * sqrt_approx(19.6f * h) * a;
        out[1 + NM * NB + b]      = (H0 - q) + inflow;
        out[1 + NM * NB + NB + b] = q;
    }

    // reset barrier state for the next graph replay (last block to exit)
    __syncthreads();
    if (tid == 0) {
        __threadfence();
        unsigned v = atomicAdd(&g_exit, 1u);
        if (v == NBLK - 1) { g_ctr = 0u; g_exit = 0u; __threadfence(); }
    }
}

// ---------------------------------------------------------------------------
extern "C" void kernel_launch(void* const* d_in, const int* in_sizes, int n_in,
                              void* d_out, int out_size)
{
    const float* H0         = (const float*)d_in[0];
    const float* H_mid      = (const float*)d_in[1];
    const float* H_last     = (const float*)d_in[2];
    const float* S0         = (const float*)d_in[3];
    const float* S_mid      = (const float*)d_in[4];
    const float* S_last     = (const float*)d_in[5];
    const float* theta0     = (const float*)d_in[6];
    const float* theta_mid  = (const float*)d_in[7];
    const float* theta_last = (const float*)d_in[8];
    const float* precip     = (const float*)d_in[9];
    float* out = (float*)d_out;

    k_cascade<<<NBLK, NTHR>>>(H0, H_mid, H_last, S0, S_mid, S_last,
                              theta0, theta_mid, theta_last, precip, out);
}

// round 9
// speedup vs baseline: 1.1811x; 1.1811x over previous
#include <cuda_runtime.h>
#include <cuda_bf16.h>
#include <cstdint>
#include <cstddef>

#define NB   1024
#define NM   14
#define NBLK 148
#define WPB  7                  // warps (=buckets) per block
#define NTHR (WPB * 32)         // 224
#define NTOT (NBLK * NTHR)      // 33152

// Inflow ping-pong buffers + barrier state. Self-resetting per launch:
// zeros at start, consumer-zeroed per layer; g_ctr/g_exit reset by the
// last-exiting block so graph replays start clean.
__device__ float    g_inflow[2][NB];
__device__ unsigned g_ctr;
__device__ unsigned g_exit;

__device__ __forceinline__ float sqrt_approx(float x) {
    float y; asm("sqrt.approx.f32 %0, %1;" : "=f"(y) : "f"(x)); return y;
}
__device__ __forceinline__ unsigned ld_acq(const unsigned* p) {
    unsigned v; asm volatile("ld.acquire.gpu.global.u32 %0, [%1];" : "=r"(v) : "l"(p)); return v;
}
__device__ __forceinline__ void l2pf(const void* p) {
    asm volatile("prefetch.global.L2 [%0];" :: "l"(p));
}

// Grid barrier: all 148 blocks resident (1 block/SM). Monotonic counter.
__device__ __forceinline__ void grid_barrier(unsigned target) {
    __syncthreads();
    if (threadIdx.x == 0) {
        __threadfence();
        atomicAdd(&g_ctr, 1u);
        while (ld_acq(&g_ctr) < target) { }
    }
    __syncthreads();
}

// Prefetch one mid layer (8 MB S + 4 MB theta = 98304 x 128B lines) into L2.
__device__ __forceinline__ void prefetch_layer(const char* Sb, const char* Tb,
                                               int l, int t) {
    const char* S = Sb + (size_t)l * 8388608;
    const char* T = Tb + (size_t)l * 4194304;
    #pragma unroll
    for (int k = 0; k < 3; ++k) {
        long line = (long)t + (long)k * NTOT;
        if (line < 65536)       l2pf(S + line * 128);
        else if (line < 98304)  l2pf(T + (line - 65536) * 128);
    }
}

// Stage a bucket row into registers: lane holds spigots {w*32+lane}.
__device__ __forceinline__ void stage_regs(const float2* __restrict__ S2,
                                           const float* __restrict__ T,
                                           int lane, float bh[32], float cc[32]) {
    const float SQ2G = 4.4271887242357310f;   // sqrt(2*9.8)
    #pragma unroll
    for (int w = 0; w < 32; ++w) {
        float2 p = S2[w * 32 + lane];
        bh[w] = p.x; cc[w] = p.y;
    }
    #pragma unroll
    for (int w = 0; w < 32; ++w)
        cc[w] = cc[w] * T[w * 32 + lane] * SQ2G;
}

// Exact sequential recurrence. Dry spigots give q==0 and leave H_eff
// bit-identical (0.5*cum is exact, fmaf(-0.5,cum,H0) == H0 - 0.5f*cum),
// so only firing spigots are serialized, lowest index first via ballot;
// windows drain in index order -> reference order preserved.
// EXTRACT>=0: also capture q of spigot (wb,lb) into qsel (head-bucket use).
template <bool ATOMIC, bool EXTRACT>
__device__ float bucket_chain(int lane, float H0, float inflow,
                              const float bh[32], const float cc[32],
                              float* __restrict__ nxt,
                              int wb, int lb, float& qsel)
{
    const unsigned FULL = 0xFFFFFFFFu;
    // spigot 0: H_eff = H0 + inflow (reference quirk)
    float bh0 = __shfl_sync(FULL, bh[0], 0);
    float cc0 = __shfl_sync(FULL, cc[0], 0);
    float h0  = fmaxf((H0 + inflow) - bh0, 0.0f);
    float q0  = cc0 * sqrt_approx(h0);
    float cum = q0;
    float H_eff = fmaf(-0.5f, cum, H0);

    float qx = 0.0f;
    #pragma unroll
    for (int w = 0; w < 32; ++w) {
        float qacc = (w == 0 && lane == 0) ? q0 : 0.0f;
        unsigned rem = (w == 0) ? 0xFFFFFFFEu : FULL;   // spigot 0 done
        while (true) {
            float h = H_eff - bh[w];
            unsigned fire = __ballot_sync(FULL, h > 0.0f) & rem;
            if (!fire) break;
            float q = cc[w] * sqrt_approx(h);            // speculative
            int f = __ffs(fire) - 1;                     // lowest firing spigot
            float qf = __shfl_sync(FULL, q, f);
            cum += qf;
            H_eff = fmaf(-0.5f, cum, H0);
            qacc = (lane == f) ? qf : qacc;
            rem &= (0xFFFFFFFEu << f);
        }
        if (EXTRACT) {
            qx = (w == wb) ? qacc : qx;
        } else if (qacc != 0.0f) {
            if (ATOMIC) atomicAdd(&nxt[w * 32 + lane], qacc);
            else        nxt[w * 32 + lane] = qacc;
        }
    }
    if (EXTRACT) qsel = __shfl_sync(FULL, qx, lb);
    return cum;
}

// ---------------------------------------------------------------------------
// Persistent kernel: 148 blocks x 224 threads, 1 block/SM, register-resident
// chains. Head bucket solved redundantly by every warp (q0 extracted from
// registers -> one fewer grid phase, no q0 memory round trip). DRAM streams
// 2 layers ahead via bounded L2 prefetch; demand staging hits L2.
// ---------------------------------------------------------------------------
__global__ void __launch_bounds__(NTHR, 1)
k_cascade(const float* __restrict__ H0p,   const float* __restrict__ H_mid,
          const float* __restrict__ H_last,const float* __restrict__ S0,
          const float* __restrict__ S_mid, const float* __restrict__ S_last,
          const float* __restrict__ theta0,const float* __restrict__ theta_mid,
          const float* __restrict__ theta_last, const float* __restrict__ precip,
          float* __restrict__ out)
{
    const int tid  = threadIdx.x;
    const int lane = tid & 31;
    const int w    = tid >> 5;                    // 0..6
    const int b    = blockIdx.x * WPB + w;        // bucket id (may be >= NB)
    const int t    = blockIdx.x * NTHR + tid;     // linear thread id

    // start the DRAM stream for layers 0 and 1 immediately
    prefetch_layer((const char*)S_mid, (const char*)theta_mid, 0, t);
    prefetch_layer((const char*)S_mid, (const char*)theta_mid, 1, t);

    if (lane == 0 && b < NB) { g_inflow[0][b] = 0.0f; g_inflow[1][b] = 0.0f; }

    const float pre      = precip[0];
    const float p_layer  = pre * (1.0f / 16.0f);
    const float p_bucket = p_layer * (1.0f / 1024.0f);

    float bh[32], cc[32];
    float q0_mine = 0.0f;
    float unused;

    // redundant head-bucket solve (identical data+ops on every warp)
    {
        stage_regs((const float2*)S0, theta0, lane, bh, cc);
        float H0h = H0p[0];
        float cum = bucket_chain<false, true>(lane, H0h, p_layer, bh, cc,
                                              nullptr, (b & 1023) >> 5, b & 31,
                                              q0_mine);
        if (blockIdx.x == 0 && w == 0 && lane == 0)
            out[0] = (H0h - cum) + p_layer;
    }

    // stage layer 0 (prefetched above -> mostly L2 hits)
    if (b < NB)
        stage_regs((const float2*)S_mid + (size_t)b * NB,
                   theta_mid + (size_t)b * NB, lane, bh, cc);

    unsigned phase = 1;
    grid_barrier(NBLK * phase); ++phase;          // inflow zeros visible

    float inflow = q0_mine + p_bucket;            // layer-0 inflow from regs

    for (int l = 0; l < NM; ++l) {
        // layer l accumulates into buf[(l+1)&1]; reads (l>=1) from buf[l&1]
        if (b < NB) {
            float H0 = H_mid[(size_t)l * NB + b];
            float cum = bucket_chain<true, false>(lane, H0, inflow, bh, cc,
                                                  g_inflow[(l + 1) & 1], 0, 0,
                                                  unused);
            if (lane == 0) out[1 + l * NB + b] = (H0 - cum) + inflow;
        }
        // stage l+1 (L2 hits) then keep the DRAM stream 2 layers ahead
        if (l + 1 < NM && b < NB) {
            size_t row = (size_t)(l + 1) * NB + (size_t)b;
            stage_regs((const float2*)S_mid + row * NB,
                       theta_mid + row * NB, lane, bh, cc);
        }
        if (l + 2 < NM)
            prefetch_layer((const char*)S_mid, (const char*)theta_mid, l + 2, t);

        grid_barrier(NBLK * phase); ++phase;      // layer-l atomics visible

        // read next inflow (published by the barrier), zero slot for reuse
        if (l + 1 < NM && b < NB) {
            float inf0 = 0.0f;
            if (lane == 0) {
                inf0 = g_inflow[(l + 1) & 1][b];
                g_inflow[(l + 1) & 1][b] = 0.0f;
            }
            inflow = __shfl_sync(0xFFFFFFFFu, inf0, 0) + p_bucket;
        }
    }

    // last layer: one outlet spigot per bucket; layer 13 wrote buf[0]
    if (b < NB && lane == 0) {
        float inflowL = g_inflow[0][b] + p_bucket;
        float H0 = H_last[b];
        float sh = S_last[2 * b + 0];
        float a  = S_last[2 * b + 1];
        float h  = fmaxf((H0 + inflowL) - sh, 0.0f);
        float q  = theta_last[b] * sqrt_approx(19.6f * h) * a;
        out[1 + NM * NB + b]      = (H0 - q) + inflowL;
        out[1 + NM * NB + NB + b] = q;
    }

    // reset barrier state for the next graph replay (last block to exit)
    __syncthreads();
    if (tid == 0) {
        __threadfence();
        unsigned v = atomicAdd(&g_exit, 1u);
        if (v == NBLK - 1) { g_ctr = 0u; g_exit = 0u; __threadfence(); }
    }
}

// ---------------------------------------------------------------------------
extern "C" void kernel_launch(void* const* d_in, const int* in_sizes, int n_in,
                              void* d_out, int out_size)
{
    const float* H0         = (const float*)d_in[0];
    const float* H_mid      = (const float*)d_in[1];
    const float* H_last     = (const float*)d_in[2];
    const float* S0         = (const float*)d_in[3];
    const float* S_mid      = (const float*)d_in[4];
    const float* S_last     = (const float*)d_in[5];
    const float* theta0     = (const float*)d_in[6];
    const float* theta_mid  = (const float*)d_in[7];
    const float* theta_last = (const float*)d_in[8];
    const float* precip     = (const float*)d_in[9];
    float* out = (float*)d_out;

    k_cascade<<<NBLK, NTHR>>>(H0, H_mid, H_last, S0, S_mid, S_last,
                              theta0, theta_mid, theta_last, precip, out);
}